// round 17
// baseline (speedup 1.0000x reference)
#include <cuda_runtime.h>
#include <math.h>

#define MAXN 32768
#define NBKT 48
#define BLK 128
#define SLOTS 256

#define FADD __fadd_rn
#define FSUB __fsub_rn
#define FMUL __fmul_rn
#define FDIV __fdiv_rn

#define EPSF   5.9604644775390625e-08f     // 2^-24
#define EPS2F  (EPSF * EPSF)
#define SAFMINF 1.1754943508222875e-38f    // 2^-126

__device__ float4 g_pos4[MAXN];

// ---------------------------------------------------------------------------
__global__ void pad_kernel(const float* __restrict__ pos, int n) {
    int i = blockIdx.x * blockDim.x + threadIdx.x;
    if (i >= n) return;
    float4 p;
    p.x = pos[3 * i + 0];
    p.y = pos[3 * i + 1];
    p.z = pos[3 * i + 2];
    p.w = 0.f;
    g_pos4[i] = p;
}

// ---------------------------------------------------------------------------
// FROZEN numeric helpers (bit-validated at rel_err 3.366292e-7).
// ---------------------------------------------------------------------------
__device__ __forceinline__ float slapy2f(float x, float y) {
    float xa = fabsf(x), ya = fabsf(y);
    float w = fmaxf(xa, ya), z = fminf(xa, ya);
    if (z == 0.f) return w;
    float t = FDIV(z, w);
    return FMUL(w, sqrtf(FADD(1.f, FMUL(t, t))));
}

// slapy2f(g, 1.f) — branch-free, bit-identical (z is never 0 here unless
// g==0, where t=0 gives w*sqrt(1)=w identically).
__device__ __forceinline__ float py21(float g) {
    float ag = fabsf(g);
    float w = fmaxf(ag, 1.f), zz = fminf(ag, 1.f);
    float tt = FDIV(zz, w);
    return FMUL(w, sqrtf(FADD(1.f, FMUL(tt, tt))));
}

// slartg in select form — bit-identical results to the branchy frozen version.
__device__ __forceinline__ void slartg_sel(float f, float g, float& c,
                                           float& s, float& r) {
    float d = sqrtf(FADD(FMUL(f, f), FMUL(g, g)));
    float p = FDIV(1.f, d);
    float cm = FMUL(fabsf(f), p);
    float sm = FMUL(g, copysignf(p, f));
    float rm = copysignf(d, f);
    bool g0 = (g == 0.f), f0 = (f == 0.f);
    c = g0 ? 1.f : (f0 ? 0.f : cm);
    s = g0 ? 0.f : (f0 ? copysignf(1.f, g) : sm);
    r = g0 ? f : (f0 ? fabsf(g) : rm);
}

__device__ void slaev2f(float a, float b, float c0, float& rt1, float& rt2,
                        float& cs1, float& sn1) {
    float sm = FADD(a, c0);
    float df = FSUB(a, c0);
    float adf = fabsf(df);
    float tb = FADD(b, b);
    float ab = fabsf(tb);
    float acmx, acmn;
    if (fabsf(a) > fabsf(c0)) { acmx = a; acmn = c0; }
    else { acmx = c0; acmn = a; }
    float rt;
    if (adf > ab) {
        float t = FDIV(ab, adf);
        rt = FMUL(adf, sqrtf(FADD(1.f, FMUL(t, t))));
    } else if (adf < ab) {
        float t = FDIV(adf, ab);
        rt = FMUL(ab, sqrtf(FADD(1.f, FMUL(t, t))));
    } else {
        rt = FMUL(ab, sqrtf(2.f));
    }
    int sgn1;
    if (sm < 0.f) {
        rt1 = FMUL(0.5f, FSUB(sm, rt)); sgn1 = -1;
        rt2 = FSUB(FMUL(FDIV(acmx, rt1), acmn), FMUL(FDIV(b, rt1), b));
    } else if (sm > 0.f) {
        rt1 = FMUL(0.5f, FADD(sm, rt)); sgn1 = 1;
        rt2 = FSUB(FMUL(FDIV(acmx, rt1), acmn), FMUL(FDIV(b, rt1), b));
    } else {
        rt1 = FMUL(0.5f, rt); rt2 = FMUL(-0.5f, rt); sgn1 = 1;
    }
    int sgn2;
    float cs;
    if (df >= 0.f) { cs = FADD(df, rt); sgn2 = 1; }
    else { cs = FSUB(df, rt); sgn2 = -1; }
    float acs = fabsf(cs);
    if (acs > ab) {
        float ct = FDIV(-tb, cs);
        sn1 = FDIV(1.f, sqrtf(FADD(1.f, FMUL(ct, ct))));
        cs1 = FMUL(ct, sn1);
    } else {
        if (ab == 0.f) { cs1 = 1.f; sn1 = 0.f; }
        else {
            float tn = FDIV(-cs, tb);
            cs1 = FDIV(1.f, sqrtf(FADD(1.f, FMUL(tn, tn))));
            sn1 = FMUL(tn, cs1);
        }
    }
    if (sgn1 == sgn2) { float tau = cs1; cs1 = -sn1; sn1 = tau; }
}

// Plane rotation on 3 Z rows: hi' = c*hi - s*lo; lo' = s*hi + c*lo.
__device__ __forceinline__ void rot_cols(float c, float s,
                                         float& h1, float& l1,
                                         float& h2, float& l2,
                                         float& h3, float& l3) {
    float t;
    t = h1; h1 = FSUB(FMUL(c, t), FMUL(s, l1)); l1 = FADD(FMUL(s, t), FMUL(c, l1));
    t = h2; h2 = FSUB(FMUL(c, t), FMUL(s, l2)); l2 = FADD(FMUL(s, t), FMUL(c, l2));
    t = h3; h3 = FSUB(FMUL(c, t), FMUL(s, l3)); l3 = FADD(FMUL(s, t), FMUL(c, l3));
}

__device__ __forceinline__ void cov_acc(float4 q, float px, float py, float pz,
                                        float& a00, float& a10, float& a20,
                                        float& a11, float& a21, float& a22) {
    float dx = FSUB(q.x, px);
    float dy = FSUB(q.y, py);
    float dz = FSUB(q.z, pz);
    a00 = FADD(a00, FMUL(dx, dx));
    a10 = FADD(a10, FMUL(dx, dy));
    a20 = FADD(a20, FMUL(dx, dz));
    a11 = FADD(a11, FMUL(dy, dy));
    a21 = FADD(a21, FMUL(dy, dz));
    a22 = FADD(a22, FMUL(dz, dz));
}

__device__ __forceinline__ bool small_e(float e, float da, float db) {
    float t = fabsf(e);
    if (t == 0.f) return true;
    return t <= FMUL(FMUL(sqrtf(fabsf(da)), sqrtf(fabsf(db))), EPSF);
}
__device__ __forceinline__ bool small_e2(float e, float da, float db) {
    float t = FMUL(e, e);
    return t <= FADD(FMUL(FMUL(EPS2F, fabsf(da)), fabsf(db)), SAFMINF);
}

// Tick types in the blk13 loop.
#define TY_DEFL1 1
#define TY_TWO12 2
#define TY_SHIFT 3
#define TY_DEFL2 4
#define TY_TWO23 5
#define TY_ABORT 6

__device__ __forceinline__ int classify(int lv, int jt, float vd1, float vd2,
                                        float vd3, float ve1, float ve2) {
    if (lv == 1) {
        if (small_e2(ve1, vd1, vd2)) return TY_DEFL1;
        if (small_e2(ve2, vd2, vd3)) return TY_TWO12;
        return (jt == 90) ? TY_ABORT : TY_SHIFT;
    }
    if (small_e2(ve2, vd2, vd3)) return TY_DEFL2;
    return TY_TWO23;
}

// One tick of the blk13 loop (frozen arithmetic), single state.
__device__ void tick_one(int ty, bool ql, int& lv, int& jt, bool& inl,
                         float& vd1, float& vd2, float& vd3,
                         float& ve1, float& ve2,
                         float& z11, float& z21, float& z31,
                         float& z12, float& z22, float& z32,
                         float& z13, float& z23, float& z33) {
    if (ty == TY_DEFL1) { ve1 = 0.f; lv = 2; return; }
    if (ty == TY_DEFL2) { ve2 = 0.f; inl = false; return; }
    if (ty == TY_ABORT) { inl = false; return; }
    if (ty == TY_TWO12) {
        ve2 = 0.f;
        float rt1, rt2, c, s;
        if (ql) {
            slaev2f(vd1, ve1, vd2, rt1, rt2, c, s);
            rot_cols(c, s, z12, z11, z22, z21, z32, z31);
            vd1 = rt1; vd2 = rt2;
        } else {
            slaev2f(vd2, ve1, vd1, rt1, rt2, c, s);
            rot_cols(c, s, z13, z12, z23, z22, z33, z32);
            vd2 = rt1; vd1 = rt2;
        }
        ve1 = 0.f;
        inl = false;
        return;
    }
    if (ty == TY_TWO23) {
        float rt1, rt2, c, s;
        if (ql) {
            slaev2f(vd2, ve2, vd3, rt1, rt2, c, s);
            rot_cols(c, s, z13, z12, z23, z22, z33, z32);
            vd2 = rt1; vd3 = rt2;
        } else {
            slaev2f(vd3, ve2, vd2, rt1, rt2, c, s);
            rot_cols(c, s, z12, z11, z22, z21, z32, z31);
            vd3 = rt1; vd2 = rt2;
        }
        ve2 = 0.f;
        inl = false;
        return;
    }
    // TY_SHIFT — frozen body
    jt++;
    float p = vd1;
    float g = FDIV(FSUB(vd2, p), FMUL(2.f, ve1));
    float r = py21(g);
    g = FADD(FSUB(vd3, p), FDIV(ve1, FADD(g, copysignf(r, g))));
    float s = 1.f, c = 1.f;
    p = 0.f;
    float wc1, wc2, ws1, ws2;
    {   // virtual i = 2
        float f = FMUL(s, ve2);
        float b = FMUL(c, ve2);
        slartg_sel(g, f, c, s, r);
        g = FSUB(vd3, p);
        r = FADD(FMUL(FSUB(vd2, g), s), FMUL(FMUL(2.f, c), b));
        p = FMUL(s, r);
        vd3 = FADD(g, p);
        g = FSUB(FMUL(c, r), b);
        wc2 = c; ws2 = -s;
    }
    {   // virtual i = 1
        float f = FMUL(s, ve1);
        float b = FMUL(c, ve1);
        slartg_sel(g, f, c, s, r);
        ve2 = r;
        g = FSUB(vd2, p);
        r = FADD(FMUL(FSUB(vd1, g), s), FMUL(FMUL(2.f, c), b));
        p = FMUL(s, r);
        vd2 = FADD(g, p);
        g = FSUB(FMUL(c, r), b);
        wc1 = c; ws1 = -s;
    }
    if (wc2 != 1.f || ws2 != 0.f) {
        if (ql) rot_cols(wc2, ws2, z13, z12, z23, z22, z33, z32);
        else    rot_cols(wc2, ws2, z11, z12, z21, z22, z31, z32);
    }
    if (wc1 != 1.f || ws1 != 0.f) {
        if (ql) rot_cols(wc1, ws1, z12, z11, z22, z21, z32, z31);
        else    rot_cols(wc1, ws1, z12, z13, z22, z23, z32, z33);
    }
    vd1 = FSUB(vd1, p);
    ve1 = g;
}

// Final sort + sormtr + store (frozen arithmetic).
__device__ void finish_state(float d1, float d2, float d3,
                             float z11, float z21, float z31,
                             float z12, float z22, float z32,
                             float z13, float z23, float z33,
                             float tau1, float v3, float* o) {
    {
        int kk = 1; float p = d1;
        if (d2 < p) { kk = 2; p = d2; }
        if (d3 < p) { kk = 3; p = d3; }
        if (kk == 2) {
            d2 = d1; d1 = p;
            float t;
            t = z11; z11 = z12; z12 = t;
            t = z21; z21 = z22; z22 = t;
            t = z31; z31 = z32; z32 = t;
        } else if (kk == 3) {
            d3 = d1; d1 = p;
            float t;
            t = z11; z11 = z13; z13 = t;
            t = z21; z21 = z23; z23 = t;
            t = z31; z31 = z33; z33 = t;
        }
    }
    if (d3 < d2) {
        float p = d2; d2 = d3; d3 = p;
        float t;
        t = z12; z12 = z13; z13 = t;
        t = z22; z22 = z23; z23 = t;
        t = z32; z32 = z33; z33 = t;
    }
    if (tau1 != 0.f) {
        float w, tt;
        w = FADD(z21, FMUL(z31, v3)); tt = FMUL(-tau1, w);
        z21 = FADD(z21, tt); z31 = FADD(z31, FMUL(v3, tt));
        w = FADD(z22, FMUL(z32, v3)); tt = FMUL(-tau1, w);
        z22 = FADD(z22, tt); z32 = FADD(z32, FMUL(v3, tt));
        w = FADD(z23, FMUL(z33, v3)); tt = FMUL(-tau1, w);
        z23 = FADD(z23, tt); z33 = FADD(z33, FMUL(v3, tt));
    }
    o[0] = z11; o[1] = z21; o[2] = z31;
    o[3] = z12; o[4] = z22; o[5] = z32;
    o[6] = z13; o[7] = z23; o[8] = z33;
}

// ---------------------------------------------------------------------------
// Fused kernel: 2 nodes/thread. cov+ssytd2 (dual-interleaved gathers) ->
// block bucket sort -> pair-solve with dual-interleaved shift iterations.
// ---------------------------------------------------------------------------
__global__ void __launch_bounds__(BLK, 1)
fused_kernel(const int* __restrict__ edge_src,
             const int* __restrict__ num_neighbors,
             float* __restrict__ out, int n, int k) {
    __shared__ float s_rec[7][SLOTS];
    __shared__ int s_gid[SLOTS];
    __shared__ unsigned char s_key[SLOTS];
    __shared__ int s_cnt[NBKT];
    __shared__ int s_off[NBKT];

    int t = threadIdx.x;
    if (t < NBKT) s_cnt[t] = 0;
    __syncthreads();

    int G = gridDim.x;
    int nodeA = blockIdx.x + t * G;
    int nodeB = blockIdx.x + (t + BLK) * G;

    bool recA = false, recB = false;
    if (nodeA < n) {
        if (num_neighbors[nodeA] <= 1) {
            float* o = out + (long long)nodeA * 9;
#pragma unroll
            for (int j = 0; j < 9; j++) o[j] = 0.f;
        } else recA = true;
    }
    if (nodeB < n) {
        if (num_neighbors[nodeB] <= 1) {
            float* o = out + (long long)nodeB * 9;
#pragma unroll
            for (int j = 0; j < 9; j++) o[j] = 0.f;
        } else recB = true;
    }

    // ========== covariance, dual-interleaved (frozen per-node order) =======
    float cA00 = 0.f, cA10 = 0.f, cA20 = 0.f, cA11 = 0.f, cA21 = 0.f, cA22 = 0.f;
    float cB00 = 0.f, cB10 = 0.f, cB20 = 0.f, cB11 = 0.f, cB21 = 0.f, cB22 = 0.f;
    {
        int sa = recA ? nodeA : 0;
        int sb = recB ? nodeB : 0;
        const int4* esA = (const int4*)(edge_src + (long long)sa * k);
        const int4* esB = (const int4*)(edge_src + (long long)sb * k);
        float4 pA = g_pos4[sa];
        float4 pB = g_pos4[sb];
#pragma unroll 4
        for (int j = 0; j < k / 4; j++) {
            int4 a4 = esA[j];
            int4 b4 = esB[j];
            float4 qa0 = __ldg(&g_pos4[a4.x]);
            float4 qb0 = __ldg(&g_pos4[b4.x]);
            float4 qa1 = __ldg(&g_pos4[a4.y]);
            float4 qb1 = __ldg(&g_pos4[b4.y]);
            float4 qa2 = __ldg(&g_pos4[a4.z]);
            float4 qb2 = __ldg(&g_pos4[b4.z]);
            float4 qa3 = __ldg(&g_pos4[a4.w]);
            float4 qb3 = __ldg(&g_pos4[b4.w]);
            cov_acc(qa0, pA.x, pA.y, pA.z, cA00, cA10, cA20, cA11, cA21, cA22);
            cov_acc(qb0, pB.x, pB.y, pB.z, cB00, cB10, cB20, cB11, cB21, cB22);
            cov_acc(qa1, pA.x, pA.y, pA.z, cA00, cA10, cA20, cA11, cA21, cA22);
            cov_acc(qb1, pB.x, pB.y, pB.z, cB00, cB10, cB20, cB11, cB21, cB22);
            cov_acc(qa2, pA.x, pA.y, pA.z, cA00, cA10, cA20, cA11, cA21, cA22);
            cov_acc(qb2, pB.x, pB.y, pB.z, cB00, cB10, cB20, cB11, cB21, cB22);
            cov_acc(qa3, pA.x, pA.y, pA.z, cA00, cA10, cA20, cA11, cA21, cA22);
            cov_acc(qb3, pB.x, pB.y, pB.z, cB00, cB10, cB20, cB11, cB21, cB22);
        }
    }

    // ========== ssytd2 + key per node (frozen), stash in registers =========
    float rA[7];
    int keyA = 0, rankA = 0;
    float rB[7];
    int keyB = 0, rankB = 0;

#pragma unroll
    for (int which = 0; which < 2; which++) {
        bool rec = (which == 0) ? recA : recB;
        if (!rec) continue;
        float a00 = (which == 0) ? cA00 : cB00;
        float a10 = (which == 0) ? cA10 : cB10;
        float a20 = (which == 0) ? cA20 : cB20;
        float a11 = (which == 0) ? cA11 : cB11;
        float a21 = (which == 0) ? cA21 : cB21;
        float a22 = (which == 0) ? cA22 : cB22;

        float d1, d2, d3, e1, e2, tau1 = 0.f, v3 = 0.f;
        {
            float alpha = a10;
            float x = a20;
            if (x == 0.f) {
                tau1 = 0.f;
                e1 = alpha;
            } else {
                float beta = -copysignf(slapy2f(alpha, x), alpha);
                tau1 = FDIV(FSUB(beta, alpha), beta);
                float rcp = FDIV(1.f, FSUB(alpha, beta));
                v3 = FMUL(x, rcp);
                e1 = beta;
                float w1 = FADD(FMUL(tau1, a11), FMUL(tau1, FMUL(a21, v3)));
                float w2 = FADD(FMUL(tau1, a21), FMUL(FMUL(tau1, v3), a22));
                float dot = FADD(w1, FMUL(w2, v3));
                float al2 = -FMUL(FMUL(0.5f, tau1), dot);
                w1 = FADD(w1, al2);
                w2 = FADD(w2, FMUL(al2, v3));
                a11 = FADD(FADD(a11, -w1), -w1);
                a21 = FADD(FADD(a21, FMUL(v3, -w1)), -w2);
                a22 = FADD(FADD(a22, FMUL(v3, -w2)), FMUL(w2, -v3));
            }
            e2 = a21;
            d1 = a00; d2 = a11; d3 = a22;
        }

        int key;
        {
            int m = 3;
            if (small_e(e1, d1, d2)) m = 1;
            else if (small_e(e2, d2, d3)) m = 2;
            int ql, cse;
            if (m == 1) {
                if (small_e(e2, d2, d3)) { ql = 0; cse = 3; }
                else {
                    ql = (fabsf(d3) < fabsf(d2)) ? 0 : 1;
                    cse = small_e2(e2, ql ? d2 : d3, ql ? d3 : d2) ? 0 : 1;
                }
                key = (ql << 2) + cse;
            } else if (m == 2) {
                ql = (fabsf(d2) < fabsf(d1)) ? 0 : 1;
                cse = small_e2(e1, ql ? d1 : d2, ql ? d2 : d1) ? 0 : 1;
                key = 8 + (ql << 2) + cse;
            } else {
                ql = (fabsf(d3) < fabsf(d1)) ? 0 : 1;
                if (ql) {
                    if (small_e2(e1, d1, d2)) cse = 0;
                    else if (small_e2(e2, d2, d3)) cse = 1;
                    else cse = 2;
                } else {
                    if (small_e2(e2, d3, d2)) cse = 0;
                    else if (small_e2(e1, d2, d1)) cse = 1;
                    else cse = 2;
                }
                if (cse == 2) {
                    float ve1 = ql ? e1 : e2;
                    float vda = ql ? d1 : d3;
                    float tst = ve1 * ve1;
                    float thr = EPS2F * fabsf(vda) * fabsf(d2) + SAFMINF;
                    float ratio = tst / thr;
                    int ex = ((__float_as_int(ratio) >> 23) & 0xFF) - 127;
                    if (ex < 0) ex = 0;
                    int diff = ex / 18;
                    if (diff > 7) diff = 7;
                    key = 32 + (ql << 3) + diff;
                } else {
                    key = 16 + (ql << 2) + cse;
                }
            }
        }
        int rank = atomicAdd(&s_cnt[key], 1);
        if (which == 0) {
            rA[0] = d1; rA[1] = d2; rA[2] = d3; rA[3] = e1; rA[4] = e2;
            rA[5] = tau1; rA[6] = v3;
            keyA = key; rankA = rank;
        } else {
            rB[0] = d1; rB[1] = d2; rB[2] = d3; rB[3] = e1; rB[4] = e2;
            rB[5] = tau1; rB[6] = v3;
            keyB = key; rankB = rank;
        }
    }
    __syncthreads();

    if (t == 0) {
        int run = 0;
#pragma unroll
        for (int b = 0; b < NBKT; b++) {
            s_off[b] = run;
            run += s_cnt[b];
        }
    }
    __syncthreads();

    if (recA) {
        int pos = s_off[keyA] + rankA;
#pragma unroll
        for (int c = 0; c < 7; c++) s_rec[c][pos] = rA[c];
        s_gid[pos] = nodeA;
        s_key[pos] = (unsigned char)keyA;
    }
    if (recB) {
        int pos = s_off[keyB] + rankB;
#pragma unroll
        for (int c = 0; c < 7; c++) s_rec[c][pos] = rB[c];
        s_gid[pos] = nodeB;
        s_key[pos] = (unsigned char)keyB;
    }
    int total = s_off[NBKT - 1] + s_cnt[NBKT - 1];
    __syncthreads();

    int iA = 2 * t;
    if (iA >= total) return;
    int iB = iA + 1;
    bool hasB = iB < total;

    // -------- load pair --------
    float d1A = s_rec[0][iA], d2A = s_rec[1][iA], d3A = s_rec[2][iA];
    float e1A = s_rec[3][iA], e2A = s_rec[4][iA];
    float tauA = s_rec[5][iA], v3A = s_rec[6][iA];
    int kA = s_key[iA], ogiA = s_gid[iA];

    int iBs = hasB ? iB : iA;
    float d1B = s_rec[0][iBs], d2B = s_rec[1][iBs], d3B = s_rec[2][iBs];
    float e1B = s_rec[3][iBs], e2B = s_rec[4][iBs];
    float tauB = s_rec[5][iBs], v3B = s_rec[6][iBs];
    int kB = s_key[iBs], ogiB = s_gid[iBs];

    float z11A = 1.f, z21A = 0.f, z31A = 0.f;
    float z12A = 0.f, z22A = 1.f, z32A = 0.f;
    float z13A = 0.f, z23A = 0.f, z33A = 1.f;
    float z11B = 1.f, z21B = 0.f, z31B = 0.f;
    float z12B = 0.f, z22B = 1.f, z32B = 0.f;
    float z13B = 0.f, z23B = 0.f, z33B = 1.f;

    // -------- per-state decode (terminal actions or loop init) --------
    bool inA = false, inB = false;
    bool qlA = false, qlB = false;
    int lvA = 1, lvB = 1, jtA = 0, jtB = 0;
    float vd1A = 0.f, vd2A = 0.f, vd3A = 0.f, ve1A = 0.f, ve2A = 0.f;
    float vd1B = 0.f, vd2B = 0.f, vd3B = 0.f, ve1B = 0.f, ve2B = 0.f;

#define DECODE(S)                                                              \
    do {                                                                       \
        int kk = k##S;                                                         \
        if (kk >= 32) {                                                        \
            ql##S = ((kk >> 3) & 1) != 0;                                      \
            in##S = true; lv##S = 1;                                           \
            if (ql##S) { vd1##S = d1##S; vd2##S = d2##S; vd3##S = d3##S;       \
                         ve1##S = e1##S; ve2##S = e2##S; }                     \
            else { vd1##S = d3##S; vd2##S = d2##S; vd3##S = d1##S;             \
                   ve1##S = e2##S; ve2##S = e1##S; }                           \
        } else if (kk >= 16) {                                                 \
            int cse = kk & 3;                                                  \
            ql##S = ((kk >> 2) & 1) != 0;                                      \
            if (cse == 0) {                                                    \
                in##S = true; lv##S = 2;                                       \
                if (ql##S) { vd1##S = d1##S; vd2##S = d2##S; vd3##S = d3##S;   \
                             ve1##S = 0.f; ve2##S = e2##S; }                   \
                else { vd1##S = d3##S; vd2##S = d2##S; vd3##S = d1##S;         \
                       ve1##S = 0.f; ve2##S = e1##S; }                         \
            } else {                                                           \
                float rt1, rt2, c, s;                                          \
                if (ql##S) {                                                   \
                    slaev2f(d1##S, e1##S, d2##S, rt1, rt2, c, s);              \
                    rot_cols(c, s, z12##S, z11##S, z22##S, z21##S,             \
                             z32##S, z31##S);                                  \
                    d1##S = rt1; d2##S = rt2;                                  \
                } else {                                                       \
                    slaev2f(d2##S, e2##S, d3##S, rt1, rt2, c, s);              \
                    rot_cols(c, s, z13##S, z12##S, z23##S, z22##S,             \
                             z33##S, z32##S);                                  \
                    d2##S = rt1; d3##S = rt2;                                  \
                }                                                              \
            }                                                                  \
        } else if (kk >= 8) {                                                  \
            if ((kk & 3) == 1) {                                               \
                float rt1, rt2, c, s;                                          \
                slaev2f(d1##S, e1##S, d2##S, rt1, rt2, c, s);                  \
                rot_cols(c, s, z12##S, z11##S, z22##S, z21##S,                 \
                         z32##S, z31##S);                                      \
                d1##S = rt1; d2##S = rt2;                                      \
            }                                                                  \
        } else {                                                               \
            if ((kk & 3) == 1) {                                               \
                float rt1, rt2, c, s;                                          \
                slaev2f(d2##S, e2##S, d3##S, rt1, rt2, c, s);                  \
                rot_cols(c, s, z13##S, z12##S, z23##S, z22##S,                 \
                         z33##S, z32##S);                                      \
                d2##S = rt1; d3##S = rt2;                                      \
            }                                                                  \
        }                                                                      \
    } while (0)

    DECODE(A);
    if (hasB) DECODE(B);
#undef DECODE

    // -------- dual loop --------
    while (inA || inB) {
        int tyA = inA ? classify(lvA, jtA, vd1A, vd2A, vd3A, ve1A, ve2A) : 0;
        int tyB = inB ? classify(lvB, jtB, vd1B, vd2B, vd3B, ve1B, ve2B) : 0;

        if (tyA == TY_SHIFT && tyB == TY_SHIFT) {
            // ===== dual-interleaved shift body (select-form, frozen bits) ===
            jtA++; jtB++;
            float pA = vd1A, pB = vd1B;
            float gA = FDIV(FSUB(vd2A, pA), FMUL(2.f, ve1A));
            float gB = FDIV(FSUB(vd2B, pB), FMUL(2.f, ve1B));
            float rA2 = py21(gA);
            float rB2 = py21(gB);
            gA = FADD(FSUB(vd3A, pA), FDIV(ve1A, FADD(gA, copysignf(rA2, gA))));
            gB = FADD(FSUB(vd3B, pB), FDIV(ve1B, FADD(gB, copysignf(rB2, gB))));
            float sA = 1.f, cA = 1.f, sB = 1.f, cB = 1.f;
            pA = 0.f; pB = 0.f;
            float wc1A, ws1A, wc2A, ws2A;
            float wc1B, ws1B, wc2B, ws2B;
            {   // virtual i = 2
                float fA = FMUL(sA, ve2A), bA = FMUL(cA, ve2A);
                float fB = FMUL(sB, ve2B), bB = FMUL(cB, ve2B);
                slartg_sel(gA, fA, cA, sA, rA2);
                slartg_sel(gB, fB, cB, sB, rB2);
                gA = FSUB(vd3A, pA);
                gB = FSUB(vd3B, pB);
                rA2 = FADD(FMUL(FSUB(vd2A, gA), sA), FMUL(FMUL(2.f, cA), bA));
                rB2 = FADD(FMUL(FSUB(vd2B, gB), sB), FMUL(FMUL(2.f, cB), bB));
                pA = FMUL(sA, rA2);
                pB = FMUL(sB, rB2);
                vd3A = FADD(gA, pA);
                vd3B = FADD(gB, pB);
                gA = FSUB(FMUL(cA, rA2), bA);
                gB = FSUB(FMUL(cB, rB2), bB);
                wc2A = cA; ws2A = -sA;
                wc2B = cB; ws2B = -sB;
            }
            {   // virtual i = 1
                float fA = FMUL(sA, ve1A), bA = FMUL(cA, ve1A);
                float fB = FMUL(sB, ve1B), bB = FMUL(cB, ve1B);
                slartg_sel(gA, fA, cA, sA, rA2);
                slartg_sel(gB, fB, cB, sB, rB2);
                ve2A = rA2;
                ve2B = rB2;
                gA = FSUB(vd2A, pA);
                gB = FSUB(vd2B, pB);
                rA2 = FADD(FMUL(FSUB(vd1A, gA), sA), FMUL(FMUL(2.f, cA), bA));
                rB2 = FADD(FMUL(FSUB(vd1B, gB), sB), FMUL(FMUL(2.f, cB), bB));
                pA = FMUL(sA, rA2);
                pB = FMUL(sB, rB2);
                vd2A = FADD(gA, pA);
                vd2B = FADD(gB, pB);
                gA = FSUB(FMUL(cA, rA2), bA);
                gB = FSUB(FMUL(cB, rB2), bB);
                wc1A = cA; ws1A = -sA;
                wc1B = cB; ws1B = -sB;
            }
            if (wc2A != 1.f || ws2A != 0.f) {
                if (qlA) rot_cols(wc2A, ws2A, z13A, z12A, z23A, z22A, z33A, z32A);
                else     rot_cols(wc2A, ws2A, z11A, z12A, z21A, z22A, z31A, z32A);
            }
            if (wc1A != 1.f || ws1A != 0.f) {
                if (qlA) rot_cols(wc1A, ws1A, z12A, z11A, z22A, z21A, z32A, z31A);
                else     rot_cols(wc1A, ws1A, z12A, z13A, z22A, z23A, z32A, z33A);
            }
            if (wc2B != 1.f || ws2B != 0.f) {
                if (qlB) rot_cols(wc2B, ws2B, z13B, z12B, z23B, z22B, z33B, z32B);
                else     rot_cols(wc2B, ws2B, z11B, z12B, z21B, z22B, z31B, z32B);
            }
            if (wc1B != 1.f || ws1B != 0.f) {
                if (qlB) rot_cols(wc1B, ws1B, z12B, z11B, z22B, z21B, z32B, z31B);
                else     rot_cols(wc1B, ws1B, z12B, z13B, z22B, z23B, z32B, z33B);
            }
            vd1A = FSUB(vd1A, pA); ve1A = gA;
            vd1B = FSUB(vd1B, pB); ve1B = gB;
        } else {
            if (tyA) tick_one(tyA, qlA, lvA, jtA, inA, vd1A, vd2A, vd3A,
                              ve1A, ve2A, z11A, z21A, z31A, z12A, z22A, z32A,
                              z13A, z23A, z33A);
            if (tyB) tick_one(tyB, qlB, lvB, jtB, inB, vd1B, vd2B, vd3B,
                              ve1B, ve2B, z11B, z21B, z31B, z12B, z22B, z32B,
                              z13B, z23B, z33B);
        }
    }

    // -------- unmirror loop states --------
    if (kA >= 32 || (kA >= 16 && (kA & 3) == 0)) {
        if (qlA) { d1A = vd1A; d2A = vd2A; d3A = vd3A; }
        else     { d3A = vd1A; d2A = vd2A; d1A = vd3A; }
    }
    if (hasB && (kB >= 32 || (kB >= 16 && (kB & 3) == 0))) {
        if (qlB) { d1B = vd1B; d2B = vd2B; d3B = vd3B; }
        else     { d3B = vd1B; d2B = vd2B; d1B = vd3B; }
    }

    finish_state(d1A, d2A, d3A, z11A, z21A, z31A, z12A, z22A, z32A,
                 z13A, z23A, z33A, tauA, v3A, out + (long long)ogiA * 9);
    if (hasB)
        finish_state(d1B, d2B, d3B, z11B, z21B, z31B, z12B, z22B, z32B,
                     z13B, z23B, z33B, tauB, v3B, out + (long long)ogiB * 9);
}

// ---------------------------------------------------------------------------
extern "C" void kernel_launch(void* const* d_in, const int* in_sizes, int n_in,
                              void* d_out, int out_size) {
    const float* pos = (const float*)d_in[0];
    const int* edge_src = (const int*)d_in[1];
    const int* num_neighbors = (const int*)d_in[3];

    int n = in_sizes[3];
    int k = in_sizes[1] / n;

    pad_kernel<<<(n + 255) / 256, 256>>>(pos, n);
    int G = 147;
    if ((long long)G * SLOTS < n) G = (n + SLOTS - 1) / SLOTS;
    fused_kernel<<<G, BLK>>>(edge_src, num_neighbors, (float*)d_out, n, k);
}